// round 1
// baseline (speedup 1.0000x reference)
#include <cuda_runtime.h>

#define B_ 2
#define L_ 512
#define S_ 512
#define H_ 8
#define E_ 32
#define D_ 64
#define LT 16      // L rows per block in scores kernel
#define LT2 16     // L rows per block in AV kernel
#define ST2 64     // S tile in AV kernel

// Scratch for softmaxed attention matrix A: (B,H,L,S) fp32 = 32 MB.
__device__ float g_A[(size_t)B_ * H_ * L_ * S_];

__device__ __forceinline__ float fast_ex2(float x) {
    float r; asm("ex2.approx.f32 %0, %1;" : "=f"(r) : "f"(x)); return r;
}
__device__ __forceinline__ float fast_rcp(float x) {
    float r; asm("rcp.approx.f32 %0, %1;" : "=f"(r) : "f"(x)); return r;
}
// tanh(x) = 1 - 2/(exp(2x)+1). ex2/rcp approx errors ~1e-6; saturates
// correctly at +/-1 for |x| large (inf -> rcp -> 0; 0 -> rcp(1)=1 -> -1).
__device__ __forceinline__ float fast_tanh(float x) {
    float t = fast_ex2(x * 2.885390082f);   // exp(2x) = 2^(x * 2/ln2)
    return fmaf(-2.f, fast_rcp(t + 1.f), 1.f);
}

// ---------------------------------------------------------------------------
// Kernel 1: scores + softmax -> g_A
// Block = (b, h, tile of LT=16 L rows). 512 threads, thread = one s.
// Each thread keeps its K row (32 floats) in registers, loops the 16 L rows
// reading q from shared (broadcast), computes score, then block softmax.
// ---------------------------------------------------------------------------
__global__ __launch_bounds__(512) void scores_kernel(
    const float* __restrict__ q, const float* __restrict__ k,
    const float* __restrict__ v, const float* __restrict__ mask,
    const float* __restrict__ klen)
{
    __shared__ float q_sh[LT * E_];
    __shared__ float v_sh[E_];
    __shared__ float s_sc[LT][S_];     // 32 KB
    __shared__ float row_red[LT];

    const int tid = threadIdx.x;       // = s
    const int bid = blockIdx.x;
    const int lt = bid & 31;           // L_/LT = 32 tiles
    const int h  = (bid >> 5) & 7;
    const int b  = bid >> 8;

    // Load 16 q rows (512 elems, one per thread) and v.
    {
        const int l = tid >> 5;
        const int e = tid & 31;
        q_sh[tid] = q[(((size_t)b * L_ + (lt * LT + l)) * H_ + h) * E_ + e];
    }
    if (tid < E_) v_sh[tid] = v[tid];
    __syncthreads();

    // K row for this s into registers (8x float4, 128B-aligned).
    float4 kr[E_ / 4];
    {
        const float4* kp = reinterpret_cast<const float4*>(
            k + (((size_t)b * S_ + tid) * H_ + h) * E_);
#pragma unroll
        for (int i = 0; i < E_ / 4; i++) kr[i] = kp[i];
    }
    const float* krf = reinterpret_cast<const float*>(kr);

    const float klen_b = klen[b * S_ + tid];

    float sc[LT];
#pragma unroll 2
    for (int l = 0; l < LT; l++) {
        float acc = 0.f;
#pragma unroll
        for (int e = 0; e < E_; e++) {
            float x = q_sh[l * E_ + e] + krf[e];
            acc = fmaf(v_sh[e], fast_tanh(x), acc);
        }
        sc[l] = acc + mask[(size_t)(lt * LT + l) * S_ + tid] + klen_b;
        s_sc[l][tid] = sc[l];
    }
    __syncthreads();

    const int warp = tid >> 5, lane = tid & 31;

    // Row max: warp w reduces row w (16 warps == 16 rows).
    if (warp < LT) {
        float m = -3.4e38f;
#pragma unroll
        for (int j = 0; j < S_ / 32; j++)
            m = fmaxf(m, s_sc[warp][lane + 32 * j]);
#pragma unroll
        for (int off = 16; off; off >>= 1)
            m = fmaxf(m, __shfl_xor_sync(0xffffffffu, m, off));
        if (lane == 0) row_red[warp] = m;
    }
    __syncthreads();

    float p[LT];
#pragma unroll
    for (int l = 0; l < LT; l++) {
        p[l] = fast_ex2((sc[l] - row_red[l]) * 1.442695041f);
        s_sc[l][tid] = p[l];
    }
    __syncthreads();

    // Row sum -> reciprocal.
    if (warp < LT) {
        float s = 0.f;
#pragma unroll
        for (int j = 0; j < S_ / 32; j++)
            s += s_sc[warp][lane + 32 * j];
#pragma unroll
        for (int off = 16; off; off >>= 1)
            s += __shfl_xor_sync(0xffffffffu, s, off);
        if (lane == 0) row_red[warp] = fast_rcp(s);
    }
    __syncthreads();

    const size_t base = (((size_t)b * H_ + h) * L_ + lt * LT) * S_ + tid;
#pragma unroll
    for (int l = 0; l < LT; l++) {
        g_A[base + (size_t)l * S_] = p[l] * row_red[l];
    }
}

// ---------------------------------------------------------------------------
// Kernel 2: out[b,l,h,d] = sum_s A[b,h,l,s] * values[b,s,h,d]
// Block = (b, h, tile of LT2=16 L rows). 256 threads: thread = (row-group, d).
// Shared-tiled GEMM, S tile = 64.
// ---------------------------------------------------------------------------
__global__ __launch_bounds__(256) void av_kernel(
    const float* __restrict__ vals, float* __restrict__ out)
{
    __shared__ float A_sh[LT2][ST2];   // 4 KB
    __shared__ float V_sh[ST2][D_];    // 16 KB

    const int tid = threadIdx.x;
    const int bid = blockIdx.x;
    const int lt = bid & 31;           // L_/LT2 = 32 tiles
    const int h  = (bid >> 5) & 7;
    const int b  = bid >> 8;

    const int d  = tid & 63;
    const int rg = tid >> 6;           // 0..3, owns rows rg*4 .. rg*4+3

    float acc[4] = {0.f, 0.f, 0.f, 0.f};

    const size_t Abase = (((size_t)b * H_ + h) * L_ + lt * LT2) * S_;

    for (int st = 0; st < S_ / ST2; st++) {
        // A tile: 16x64 = 1024 elems, 4 per thread.
#pragma unroll
        for (int i = 0; i < 4; i++) {
            int idx = tid + i * 256;
            int row = idx >> 6, col = idx & 63;
            A_sh[row][col] = g_A[Abase + (size_t)row * S_ + st * ST2 + col];
        }
        // V tile: 64x64 = 4096 elems, 16 per thread.
#pragma unroll
        for (int i = 0; i < 16; i++) {
            int idx = tid + i * 256;
            int row = idx >> 6, col = idx & 63;
            V_sh[row][col] =
                vals[(((size_t)b * S_ + st * ST2 + row) * H_ + h) * D_ + col];
        }
        __syncthreads();

#pragma unroll 4
        for (int s4 = 0; s4 < ST2 / 4; s4++) {
            float vv0 = V_sh[s4 * 4 + 0][d];
            float vv1 = V_sh[s4 * 4 + 1][d];
            float vv2 = V_sh[s4 * 4 + 2][d];
            float vv3 = V_sh[s4 * 4 + 3][d];
#pragma unroll
            for (int r = 0; r < 4; r++) {
                float4 a = *reinterpret_cast<const float4*>(
                    &A_sh[rg * 4 + r][s4 * 4]);
                acc[r] = fmaf(a.x, vv0,
                         fmaf(a.y, vv1,
                         fmaf(a.z, vv2,
                         fmaf(a.w, vv3, acc[r]))));
            }
        }
        __syncthreads();
    }

#pragma unroll
    for (int r = 0; r < 4; r++) {
        out[(((size_t)b * L_ + lt * LT2 + rg * 4 + r) * H_ + h) * D_ + d] = acc[r];
    }
}

extern "C" void kernel_launch(void* const* d_in, const int* in_sizes, int n_in,
                              void* d_out, int out_size)
{
    const float* q    = (const float*)d_in[0];   // (B,L,H,E)
    const float* k    = (const float*)d_in[1];   // (B,S,H,E)
    const float* vals = (const float*)d_in[2];   // (B,S,H,D)
    const float* v    = (const float*)d_in[3];   // (E,)
    const float* mask = (const float*)d_in[4];   // (L,S)
    const float* klen = (const float*)d_in[5];   // (B,S)
    float* out = (float*)d_out;                  // (B,L,H,D)

    scores_kernel<<<B_ * H_ * (L_ / LT), 512>>>(q, k, v, mask, klen);
    av_kernel<<<B_ * H_ * (L_ / LT2), 256>>>(vals, out);
}

// round 4
// speedup vs baseline: 1.1183x; 1.1183x over previous
#include <cuda_runtime.h>

#define B_ 2
#define L_ 512
#define S_ 512
#define H_ 8
#define E_ 32
#define D_ 64
#define LT 16        // L rows per block
#define ST 128       // S tile for V in AV phase
#define VPAD 132     // V_shT row stride (mult of 4, mod 32 == 4)

__device__ __forceinline__ float fast_ex2(float x) {
    float r; asm("ex2.approx.f32 %0, %1;" : "=f"(r) : "f"(x)); return r;
}
__device__ __forceinline__ float fast_rcp(float x) {
    float r; asm("rcp.approx.f32 %0, %1;" : "=f"(r) : "f"(x)); return r;
}

// Fused: scores (exact tanh via ex2+rcp) + softmax + A@V.
// Block = (b, h, 16 L rows). 512 threads; score phase: thread = s.
// AV phase: thread = (rowpair, d).
__global__ __launch_bounds__(512, 2) void addattn_kernel(
    const float* __restrict__ q, const float* __restrict__ k,
    const float* __restrict__ v, const float* __restrict__ vals,
    const float* __restrict__ mask, const float* __restrict__ klen,
    float* __restrict__ out)
{
    __shared__ float q_sh[LT * E_];        // pre-scaled by 2/ln2
    __shared__ float v_sh[E_];
    __shared__ float s_sc[LT][S_];         // scores -> exp(p), 32 KB
    __shared__ float row_red[LT];
    __shared__ float V_shT[D_][VPAD];      // transposed V tile, 33 KB

    const int tid = threadIdx.x;           // = s in score phase
    const int bid = blockIdx.x;
    const int lt = bid & 31;               // 32 L-tiles
    const int h  = (bid >> 5) & 7;
    const int b  = bid >> 8;
    const float C = 2.885390082f;          // 2/ln2

    // ---- loads -----------------------------------------------------------
    {
        const int l = tid >> 5, e = tid & 31;
        q_sh[tid] = C * q[(((size_t)b * L_ + (lt * LT + l)) * H_ + h) * E_ + e];
    }
    if (tid < E_) v_sh[tid] = v[tid];
    __syncthreads();

    // K row for this s, pre-scaled, in registers.
    float4 kr[E_ / 4];
    {
        const float4* kp = reinterpret_cast<const float4*>(
            k + (((size_t)b * S_ + tid) * H_ + h) * E_);
#pragma unroll
        for (int i = 0; i < E_ / 4; i++) {
            float4 t = kp[i];
            t.x *= C; t.y *= C; t.z *= C; t.w *= C;
            kr[i] = t;
        }
    }
    const float* krf = reinterpret_cast<const float*>(kr);

    float vsum = 0.f;
#pragma unroll
    for (int e = 0; e < E_; e++) vsum += v_sh[e];

    const float klen_b = klen[b * S_ + tid];

    // ---- scores: sc = vsum - 2*sum_e v_e/(1+exp(2(q+k))) + masks ---------
#pragma unroll 2
    for (int l = 0; l < LT; l++) {
        float acc = 0.f;
#pragma unroll
        for (int e = 0; e < E_; e++) {
            float t = fast_ex2(q_sh[l * E_ + e] + krf[e]);   // exp(2x)
            acc = fmaf(v_sh[e], fast_rcp(t + 1.f), acc);
        }
        s_sc[l][tid] = fmaf(-2.f, acc, vsum)
                     + mask[(size_t)(lt * LT + l) * S_ + tid] + klen_b;
    }
    __syncthreads();

    const int warp = tid >> 5, lane = tid & 31;

    // ---- row max (warp w owns row w) ------------------------------------
    {
        float m = -3.4e38f;
#pragma unroll
        for (int j = 0; j < S_ / 32; j++)
            m = fmaxf(m, s_sc[warp][lane + 32 * j]);
#pragma unroll
        for (int off = 16; off; off >>= 1)
            m = fmaxf(m, __shfl_xor_sync(0xffffffffu, m, off));
        if (lane == 0) row_red[warp] = m;
    }
    __syncthreads();

    // ---- exp (unnormalized) in place ------------------------------------
#pragma unroll
    for (int l = 0; l < LT; l++) {
        float m = row_red[l];
        s_sc[l][tid] = fast_ex2((s_sc[l][tid] - m) * 1.442695041f);
    }
    __syncthreads();

    // ---- row sum -> reciprocal ------------------------------------------
    {
        float s = 0.f;
#pragma unroll
        for (int j = 0; j < S_ / 32; j++)
            s += s_sc[warp][lane + 32 * j];
#pragma unroll
        for (int off = 16; off; off >>= 1)
            s += __shfl_xor_sync(0xffffffffu, s, off);
        if (lane == 0) row_red[warp] = fast_rcp(s);
    }
    __syncthreads();

    // ---- AV: out[16][64] = P[16][512] @ V[512][64], normalize at end -----
    const int d  = tid & 63;
    const int rg = tid >> 6;               // 0..7, owns rows 2rg, 2rg+1
    const int r0 = rg * 2, r1 = r0 + 1;
    float acc0 = 0.f, acc1 = 0.f;

    for (int st = 0; st < S_ / ST; st++) {
        // Load V tile transposed: V_shT[d][s] (stride 132: STS 4-way
        // conflict but cheap; LDS.128 reads conflict-free per quarter-warp).
#pragma unroll
        for (int i = 0; i < (ST * D_) / 512; i++) {   // 16 elems/thread
            int idx = tid + i * 512;
            int srow = idx >> 6, dcol = idx & 63;
            V_shT[dcol][srow] =
                vals[(((size_t)b * S_ + st * ST + srow) * H_ + h) * D_ + dcol];
        }
        __syncthreads();

#pragma unroll 8
        for (int s4 = 0; s4 < ST / 4; s4++) {
            float4 a0 = *reinterpret_cast<const float4*>(&s_sc[r0][st * ST + s4 * 4]);
            float4 a1 = *reinterpret_cast<const float4*>(&s_sc[r1][st * ST + s4 * 4]);
            float4 vv = *reinterpret_cast<const float4*>(&V_shT[d][s4 * 4]);
            acc0 = fmaf(a0.x, vv.x, fmaf(a0.y, vv.y,
                   fmaf(a0.z, vv.z, fmaf(a0.w, vv.w, acc0))));
            acc1 = fmaf(a1.x, vv.x, fmaf(a1.y, vv.y,
                   fmaf(a1.z, vv.z, fmaf(a1.w, vv.w, acc1))));
        }
        __syncthreads();
    }

    const float n0 = row_red[r0], n1 = row_red[r1];
    out[(((size_t)b * L_ + lt * LT + r0) * H_ + h) * D_ + d] = acc0 * n0;
    out[(((size_t)b * L_ + lt * LT + r1) * H_ + h) * D_ + d] = acc1 * n1;
}

extern "C" void kernel_launch(void* const* d_in, const int* in_sizes, int n_in,
                              void* d_out, int out_size)
{
    const float* q    = (const float*)d_in[0];   // (B,L,H,E)
    const float* k    = (const float*)d_in[1];   // (B,S,H,E)
    const float* vals = (const float*)d_in[2];   // (B,S,H,D)
    const float* v    = (const float*)d_in[3];   // (E,)
    const float* mask = (const float*)d_in[4];   // (L,S)
    const float* klen = (const float*)d_in[5];   // (B,S)
    float* out = (float*)d_out;                  // (B,L,H,D)

    addattn_kernel<<<B_ * H_ * (L_ / LT), 512>>>(q, k, v, vals, mask, klen, out);
}

// round 6
// speedup vs baseline: 1.2338x; 1.1033x over previous
#include <cuda_runtime.h>

#define B_ 2
#define L_ 512
#define S_ 512
#define H_ 8
#define E_ 32
#define D_ 64
#define LT 16        // L rows per block
#define ST 128       // S tile for V in AV phase
#define VPAD 132     // V_shT row stride (mult of 4, mod 32 == 4)

__device__ __forceinline__ float fast_ex2(float x) {
    float r; asm("ex2.approx.f32 %0, %1;" : "=f"(r) : "f"(x)); return r;
}
__device__ __forceinline__ float fast_rcp(float x) {
    float r; asm("rcp.approx.f32 %0, %1;" : "=f"(r) : "f"(x)); return r;
}

// Fused additive attention. tanh(q+k) evaluated via the separable form
//   tanh(x) = 1 - 2/(1 + exp(2q)exp(2k)),  exp(2q), exp(2k) PREcomputed,
// so the inner loop has 1 MUFU (rcp) instead of 2 (ex2+rcp).
// Block = (b, h, 16 L rows). 512 threads; score phase: thread = s.
__global__ __launch_bounds__(512, 2) void addattn_kernel(
    const float* __restrict__ q, const float* __restrict__ k,
    const float* __restrict__ v, const float* __restrict__ vals,
    const float* __restrict__ mask, const float* __restrict__ klen,
    float* __restrict__ out)
{
    __shared__ float eq_sh[LT * E_];       // exp2(C*q)
    __shared__ float v_sh[E_];
    __shared__ float s_sc[LT][S_];         // scores -> exp(p), 32 KB
    __shared__ float row_red[LT];
    __shared__ float V_shT[D_][VPAD];      // transposed V tile, 33 KB

    const int tid = threadIdx.x;           // = s in score phase
    const int bid = blockIdx.x;
    const int lt = bid & 31;               // 32 L-tiles
    const int h  = (bid >> 5) & 7;
    const int b  = bid >> 8;
    const float C = 2.885390082f;          // 2/ln2

    // ---- loads -----------------------------------------------------------
    {
        const int l = tid >> 5, e = tid & 31;
        eq_sh[tid] = fast_ex2(
            C * q[(((size_t)b * L_ + (lt * LT + l)) * H_ + h) * E_ + e]);
    }
    if (tid < E_) v_sh[tid] = v[tid];
    __syncthreads();

    // Ek row for this s in registers: exp2(C*k).
    float4 kr[E_ / 4];
    {
        const float4* kp = reinterpret_cast<const float4*>(
            k + (((size_t)b * S_ + tid) * H_ + h) * E_);
#pragma unroll
        for (int i = 0; i < E_ / 4; i++) {
            float4 t = kp[i];
            t.x = fast_ex2(C * t.x); t.y = fast_ex2(C * t.y);
            t.z = fast_ex2(C * t.z); t.w = fast_ex2(C * t.w);
            kr[i] = t;
        }
    }
    const float* ekf = reinterpret_cast<const float*>(kr);

    float vsum = 0.f;
#pragma unroll
    for (int e = 0; e < E_; e++) vsum += v_sh[e];

    const float klen_b = klen[b * S_ + tid];

    // ---- scores: sc = vsum - 2*sum_e v_e/(1 + Eq*Ek) + masks -------------
#pragma unroll 2
    for (int l = 0; l < LT; l++) {
        float acc = 0.f;
#pragma unroll
        for (int e = 0; e < E_; e++) {
            float t = fmaf(eq_sh[l * E_ + e], ekf[e], 1.f);
            acc = fmaf(v_sh[e], fast_rcp(t), acc);
        }
        s_sc[l][tid] = fmaf(-2.f, acc, vsum)
                     + mask[(size_t)(lt * LT + l) * S_ + tid] + klen_b;
    }
    __syncthreads();

    const int warp = tid >> 5, lane = tid & 31;

    // ---- row max (warp w owns row w) ------------------------------------
    {
        float m = -3.4e38f;
#pragma unroll
        for (int j = 0; j < S_ / 32; j++)
            m = fmaxf(m, s_sc[warp][lane + 32 * j]);
#pragma unroll
        for (int off = 16; off; off >>= 1)
            m = fmaxf(m, __shfl_xor_sync(0xffffffffu, m, off));
        if (lane == 0) row_red[warp] = m;
    }
    __syncthreads();

    // ---- exp (unnormalized) in place ------------------------------------
#pragma unroll
    for (int l = 0; l < LT; l++) {
        float m = row_red[l];
        s_sc[l][tid] = fast_ex2((s_sc[l][tid] - m) * 1.442695041f);
    }
    __syncthreads();

    // ---- row sum -> reciprocal ------------------------------------------
    {
        float s = 0.f;
#pragma unroll
        for (int j = 0; j < S_ / 32; j++)
            s += s_sc[warp][lane + 32 * j];
#pragma unroll
        for (int off = 16; off; off >>= 1)
            s += __shfl_xor_sync(0xffffffffu, s, off);
        if (lane == 0) row_red[warp] = fast_rcp(s);
    }
    __syncthreads();

    // ---- AV: out[16][64] = P[16][512] @ V[512][64], normalize at end -----
    const int d  = tid & 63;
    const int rg = tid >> 6;               // 0..7, owns rows 2rg, 2rg+1
    const int r0 = rg * 2, r1 = r0 + 1;
    float acc0 = 0.f, acc1 = 0.f;

    for (int st = 0; st < S_ / ST; st++) {
        // V tile transposed: V_shT[d][s]; LDS.128 reads conflict-free.
#pragma unroll
        for (int i = 0; i < (ST * D_) / 512; i++) {   // 16 elems/thread
            int idx = tid + i * 512;
            int srow = idx >> 6, dcol = idx & 63;
            V_shT[dcol][srow] =
                vals[(((size_t)b * S_ + st * ST + srow) * H_ + h) * D_ + dcol];
        }
        __syncthreads();

#pragma unroll 8
        for (int s4 = 0; s4 < ST / 4; s4++) {
            float4 a0 = *reinterpret_cast<const float4*>(&s_sc[r0][st * ST + s4 * 4]);
            float4 a1 = *reinterpret_cast<const float4*>(&s_sc[r1][st * ST + s4 * 4]);
            float4 vv = *reinterpret_cast<const float4*>(&V_shT[d][s4 * 4]);
            acc0 = fmaf(a0.x, vv.x, fmaf(a0.y, vv.y,
                   fmaf(a0.z, vv.z, fmaf(a0.w, vv.w, acc0))));
            acc1 = fmaf(a1.x, vv.x, fmaf(a1.y, vv.y,
                   fmaf(a1.z, vv.z, fmaf(a1.w, vv.w, acc1))));
        }
        __syncthreads();
    }

    const float n0 = row_red[r0], n1 = row_red[r1];
    out[(((size_t)b * L_ + lt * LT + r0) * H_ + h) * D_ + d] = acc0 * n0;
    out[(((size_t)b * L_ + lt * LT + r1) * H_ + h) * D_ + d] = acc1 * n1;
}

extern "C" void kernel_launch(void* const* d_in, const int* in_sizes, int n_in,
                              void* d_out, int out_size)
{
    const float* q    = (const float*)d_in[0];   // (B,L,H,E)
    const float* k    = (const float*)d_in[1];   // (B,S,H,E)
    const float* vals = (const float*)d_in[2];   // (B,S,H,D)
    const float* v    = (const float*)d_in[3];   // (E,)
    const float* mask = (const float*)d_in[4];   // (L,S)
    const float* klen = (const float*)d_in[5];   // (B,S)
    float* out = (float*)d_out;                  // (B,L,H,D)

    addattn_kernel<<<B_ * H_ * (L_ / LT), 512>>>(q, k, v, vals, mask, klen, out);
}

// round 8
// speedup vs baseline: 1.4090x; 1.1420x over previous
#include <cuda_runtime.h>

#define B_ 2
#define L_ 512
#define S_ 512
#define H_ 8
#define E_ 32
#define D_ 64
#define LT 16        // L rows per block
#define ST 128       // S tile for V in AV phase
#define VPAD 132     // V_shT row stride (mult of 4, mod 32 == 4)

__device__ __forceinline__ float fast_ex2(float x) {
    float r; asm("ex2.approx.f32 %0, %1;" : "=f"(r) : "f"(x)); return r;
}
__device__ __forceinline__ float fast_rcp(float x) {
    float r; asm("rcp.approx.f32 %0, %1;" : "=f"(r) : "f"(x)); return r;
}

// Fused additive attention, separable-exp tanh:
//   tanh(q+k) = 1 - 2/(1 + exp2(Cq)exp2(Ck)),  C = 2/ln2.
// Score inner loop: 1 LDS.128 + 8 FFMA + 4 MUFU per 4 elements; ek and v
// register-resident. Block = (b, h, 16 L rows); 512 threads, thread = s.
__global__ __launch_bounds__(512, 2) void addattn_kernel(
    const float* __restrict__ q, const float* __restrict__ k,
    const float* __restrict__ v, const float* __restrict__ vals,
    const float* __restrict__ mask, const float* __restrict__ klen,
    float* __restrict__ out)
{
    __shared__ float eq_sh[LT * E_];       // exp2(C*q), [l][e]
    __shared__ float v_sh[E_];
    __shared__ float s_sc[LT][S_];         // scores -> exp(p), 32 KB
    __shared__ float row_red[LT];
    __shared__ float V_shT[D_][VPAD];      // transposed V tile, 33 KB

    const int tid = threadIdx.x;           // = s in score phase
    const int bid = blockIdx.x;
    const int lt = bid & 31;               // 32 L-tiles
    const int h  = (bid >> 5) & 7;
    const int b  = bid >> 8;
    const float C = 2.885390082f;          // 2/ln2

    // ---- stage q (as exp2) and v into shared ----------------------------
    {
        const int l = tid >> 5, e = tid & 31;
        eq_sh[tid] = fast_ex2(
            C * q[(((size_t)b * L_ + (lt * LT + l)) * H_ + h) * E_ + e]);
    }
    if (tid < E_) v_sh[tid] = v[tid];
    __syncthreads();

    float vsum = 0.f;
#pragma unroll
    for (int e = 0; e < E_; e++) vsum += v_sh[e];
    const float klen_b = klen[b * S_ + tid];

    const float4* kp = reinterpret_cast<const float4*>(
        k + (((size_t)b * S_ + tid) * H_ + h) * E_);

    // ---- scores: acc[l] = sum_e v_e / (1 + Eq*Ek) ------------------------
    float acc[LT];
#pragma unroll
    for (int l = 0; l < LT; l++) acc[l] = 0.f;

#pragma unroll
    for (int eh = 0; eh < 2; eh++) {       // e-halves: ek half in 16 regs
        float ek[16];
#pragma unroll
        for (int i = 0; i < 4; i++) {
            float4 t = kp[eh * 4 + i];
            ek[i * 4 + 0] = fast_ex2(C * t.x);
            ek[i * 4 + 1] = fast_ex2(C * t.y);
            ek[i * 4 + 2] = fast_ex2(C * t.z);
            ek[i * 4 + 3] = fast_ex2(C * t.w);
        }
#pragma unroll
        for (int e4 = 0; e4 < 4; e4++) {
            const float4 v4 = *reinterpret_cast<const float4*>(
                &v_sh[eh * 16 + e4 * 4]);
            const float ek0 = ek[e4 * 4 + 0], ek1 = ek[e4 * 4 + 1];
            const float ek2 = ek[e4 * 4 + 2], ek3 = ek[e4 * 4 + 3];
#pragma unroll
            for (int l = 0; l < LT; l++) {
                const float4 eq4 = *reinterpret_cast<const float4*>(
                    &eq_sh[l * E_ + eh * 16 + e4 * 4]);
                float r0 = fast_rcp(fmaf(eq4.x, ek0, 1.f));
                float r1 = fast_rcp(fmaf(eq4.y, ek1, 1.f));
                float r2 = fast_rcp(fmaf(eq4.z, ek2, 1.f));
                float r3 = fast_rcp(fmaf(eq4.w, ek3, 1.f));
                acc[l] = fmaf(v4.x, r0, fmaf(v4.y, r1,
                         fmaf(v4.z, r2, fmaf(v4.w, r3, acc[l]))));
            }
        }
    }

    // sc = vsum - 2*acc + masks
#pragma unroll
    for (int l = 0; l < LT; l++) {
        s_sc[l][tid] = fmaf(-2.f, acc[l], vsum)
                     + mask[(size_t)(lt * LT + l) * S_ + tid] + klen_b;
    }
    __syncthreads();

    // ---- fused max + exp + sum: warp w owns row w ------------------------
    {
        const int warp = tid >> 5, lane = tid & 31;
        float x[S_ / 32];
#pragma unroll
        for (int j = 0; j < S_ / 32; j++) x[j] = s_sc[warp][lane + 32 * j];

        float mx = x[0];
#pragma unroll
        for (int j = 1; j < S_ / 32; j++) mx = fmaxf(mx, x[j]);
#pragma unroll
        for (int off = 16; off; off >>= 1)
            mx = fmaxf(mx, __shfl_xor_sync(0xffffffffu, mx, off));

        float s = 0.f;
#pragma unroll
        for (int j = 0; j < S_ / 32; j++) {
            float p = fast_ex2((x[j] - mx) * 1.442695041f);
            s_sc[warp][lane + 32 * j] = p;
            s += p;
        }
#pragma unroll
        for (int off = 16; off; off >>= 1)
            s += __shfl_xor_sync(0xffffffffu, s, off);
        if (lane == 0) row_red[warp] = fast_rcp(s);
    }
    __syncthreads();

    // ---- AV: out[16][64] = P[16][512] @ V[512][64], normalize at end -----
    const int d  = tid & 63;
    const int rg = tid >> 6;               // 0..7, owns rows 2rg, 2rg+1
    const int r0 = rg * 2, r1 = r0 + 1;
    float acc0 = 0.f, acc1 = 0.f;

    for (int st = 0; st < S_ / ST; st++) {
        // V tile transposed: V_shT[d][s]; LDS.128 reads conflict-free.
#pragma unroll
        for (int i = 0; i < (ST * D_) / 512; i++) {   // 16 elems/thread
            int idx = tid + i * 512;
            int srow = idx >> 6, dcol = idx & 63;
            V_shT[dcol][srow] =
                vals[(((size_t)b * S_ + st * ST + srow) * H_ + h) * D_ + dcol];
        }
        __syncthreads();

#pragma unroll 8
        for (int s4 = 0; s4 < ST / 4; s4++) {
            float4 a0 = *reinterpret_cast<const float4*>(&s_sc[r0][st * ST + s4 * 4]);
            float4 a1 = *reinterpret_cast<const float4*>(&s_sc[r1][st * ST + s4 * 4]);
            float4 vv = *reinterpret_cast<const float4*>(&V_shT[d][s4 * 4]);
            acc0 = fmaf(a0.x, vv.x, fmaf(a0.y, vv.y,
                   fmaf(a0.z, vv.z, fmaf(a0.w, vv.w, acc0))));
            acc1 = fmaf(a1.x, vv.x, fmaf(a1.y, vv.y,
                   fmaf(a1.z, vv.z, fmaf(a1.w, vv.w, acc1))));
        }
        __syncthreads();
    }

    const float n0 = row_red[r0], n1 = row_red[r1];
    out[(((size_t)b * L_ + lt * LT + r0) * H_ + h) * D_ + d] = acc0 * n0;
    out[(((size_t)b * L_ + lt * LT + r1) * H_ + h) * D_ + d] = acc1 * n1;
}

extern "C" void kernel_launch(void* const* d_in, const int* in_sizes, int n_in,
                              void* d_out, int out_size)
{
    const float* q    = (const float*)d_in[0];   // (B,L,H,E)
    const float* k    = (const float*)d_in[1];   // (B,S,H,E)
    const float* vals = (const float*)d_in[2];   // (B,S,H,D)
    const float* v    = (const float*)d_in[3];   // (E,)
    const float* mask = (const float*)d_in[4];   // (L,S)
    const float* klen = (const float*)d_in[5];   // (B,S)
    float* out = (float*)d_out;                  // (B,L,H,D)

    addattn_kernel<<<B_ * H_ * (L_ / LT), 512>>>(q, k, v, vals, mask, klen, out);
}

// round 13
// speedup vs baseline: 1.4437x; 1.0246x over previous
#include <cuda_runtime.h>

#define B_ 2
#define L_ 512
#define S_ 512
#define H_ 8
#define E_ 32
#define D_ 64
#define LT 16        // L rows per block
#define ST 128       // S tile for V in AV phase
#define VPAD 132     // V_shT row stride (mult of 4, mod 32 == 4)

__device__ __forceinline__ float fast_ex2(float x) {
    float r; asm("ex2.approx.f32 %0, %1;" : "=f"(r) : "f"(x)); return r;
}
__device__ __forceinline__ float fast_rcp(float x) {
    float r; asm("rcp.approx.f32 %0, %1;" : "=f"(r) : "f"(x)); return r;
}

// Fused additive attention, separable-exp tanh:
//   tanh(q+k) = 1 - 2/(1 + exp2(Cq)exp2(Ck)),  C = 2/ln2.
// Occupancy-3 variant: only 4 ek values live at a time (outer e-quad loop),
// so regs fit 1536 threads/SM. Block = (b,h,16 L rows); thread = s.
__global__ __launch_bounds__(512, 3) void addattn_kernel(
    const float* __restrict__ q, const float* __restrict__ k,
    const float* __restrict__ v, const float* __restrict__ vals,
    const float* __restrict__ mask, const float* __restrict__ klen,
    float* __restrict__ out)
{
    __shared__ float eq_sh[LT * E_];       // exp2(C*q), [l][e]
    __shared__ float v_sh[E_];
    __shared__ float s_sc[LT][S_];         // scores -> exp(p), 32 KB
    __shared__ float row_red[LT];
    __shared__ float V_shT[D_][VPAD];      // transposed V tile, 33 KB

    const int tid = threadIdx.x;           // = s in score phase
    const int bid = blockIdx.x;
    const int lt = bid & 31;               // 32 L-tiles
    const int h  = (bid >> 5) & 7;
    const int b  = bid >> 8;
    const float C = 2.885390082f;          // 2/ln2

    // ---- stage q (as exp2) and v into shared ----------------------------
    {
        const int l = tid >> 5, e = tid & 31;
        eq_sh[tid] = fast_ex2(
            C * q[(((size_t)b * L_ + (lt * LT + l)) * H_ + h) * E_ + e]);
    }
    if (tid < E_) v_sh[tid] = v[tid];
    __syncthreads();

    float vsum = 0.f;
#pragma unroll
    for (int e = 0; e < E_; e++) vsum += v_sh[e];
    const float klen_b = klen[b * S_ + tid];

    const float4* kp = reinterpret_cast<const float4*>(
        k + (((size_t)b * S_ + tid) * H_ + h) * E_);

    // ---- scores: acc[l] = sum_e v_e / (1 + Eq*Ek) ------------------------
    float acc[LT];
#pragma unroll
    for (int l = 0; l < LT; l++) acc[l] = 0.f;

#pragma unroll
    for (int e4 = 0; e4 < E_ / 4; e4++) {  // e-quads: only 4 ek live
        const float4 kt = kp[e4];
        const float ek0 = fast_ex2(C * kt.x);
        const float ek1 = fast_ex2(C * kt.y);
        const float ek2 = fast_ex2(C * kt.z);
        const float ek3 = fast_ex2(C * kt.w);
        const float4 v4 = *reinterpret_cast<const float4*>(&v_sh[e4 * 4]);
#pragma unroll
        for (int l = 0; l < LT; l++) {
            const float4 eq4 = *reinterpret_cast<const float4*>(
                &eq_sh[l * E_ + e4 * 4]);
            float r0 = fast_rcp(fmaf(eq4.x, ek0, 1.f));
            float r1 = fast_rcp(fmaf(eq4.y, ek1, 1.f));
            float r2 = fast_rcp(fmaf(eq4.z, ek2, 1.f));
            float r3 = fast_rcp(fmaf(eq4.w, ek3, 1.f));
            acc[l] = fmaf(v4.x, r0, fmaf(v4.y, r1,
                     fmaf(v4.z, r2, fmaf(v4.w, r3, acc[l]))));
        }
    }

    // sc = vsum - 2*acc + masks
#pragma unroll
    for (int l = 0; l < LT; l++) {
        s_sc[l][tid] = fmaf(-2.f, acc[l], vsum)
                     + mask[(size_t)(lt * LT + l) * S_ + tid] + klen_b;
    }
    __syncthreads();

    // ---- fused max + exp + sum: warp w owns row w ------------------------
    {
        const int warp = tid >> 5, lane = tid & 31;
        float x[S_ / 32];
#pragma unroll
        for (int j = 0; j < S_ / 32; j++) x[j] = s_sc[warp][lane + 32 * j];

        float mx = x[0];
#pragma unroll
        for (int j = 1; j < S_ / 32; j++) mx = fmaxf(mx, x[j]);
#pragma unroll
        for (int off = 16; off; off >>= 1)
            mx = fmaxf(mx, __shfl_xor_sync(0xffffffffu, mx, off));

        float s = 0.f;
#pragma unroll
        for (int j = 0; j < S_ / 32; j++) {
            float p = fast_ex2((x[j] - mx) * 1.442695041f);
            s_sc[warp][lane + 32 * j] = p;
            s += p;
        }
#pragma unroll
        for (int off = 16; off; off >>= 1)
            s += __shfl_xor_sync(0xffffffffu, s, off);
        if (lane == 0) row_red[warp] = fast_rcp(s);
    }
    __syncthreads();

    // ---- AV: out[16][64] = P[16][512] @ V[512][64], normalize at end -----
    const int d  = tid & 63;
    const int rg = tid >> 6;               // 0..7, owns rows 2rg, 2rg+1
    const int r0 = rg * 2, r1 = r0 + 1;
    float acc0 = 0.f, acc1 = 0.f;

    for (int st = 0; st < S_ / ST; st++) {
        // V tile transposed: V_shT[d][s]; LDS.128 reads conflict-free.
#pragma unroll
        for (int i = 0; i < (ST * D_) / 512; i++) {   // 16 elems/thread
            int idx = tid + i * 512;
            int srow = idx >> 6, dcol = idx & 63;
            V_shT[dcol][srow] =
                vals[(((size_t)b * S_ + st * ST + srow) * H_ + h) * D_ + dcol];
        }
        __syncthreads();

#pragma unroll 8
        for (int s4 = 0; s4 < ST / 4; s4++) {
            float4 a0 = *reinterpret_cast<const float4*>(&s_sc[r0][st * ST + s4 * 4]);
            float4 a1 = *reinterpret_cast<const float4*>(&s_sc[r1][st * ST + s4 * 4]);
            float4 vv = *reinterpret_cast<const float4*>(&V_shT[d][s4 * 4]);
            acc0 = fmaf(a0.x, vv.x, fmaf(a0.y, vv.y,
                   fmaf(a0.z, vv.z, fmaf(a0.w, vv.w, acc0))));
            acc1 = fmaf(a1.x, vv.x, fmaf(a1.y, vv.y,
                   fmaf(a1.z, vv.z, fmaf(a1.w, vv.w, acc1))));
        }
        __syncthreads();
    }

    const float n0 = row_red[r0], n1 = row_red[r1];
    out[(((size_t)b * L_ + lt * LT + r0) * H_ + h) * D_ + d] = acc0 * n0;
    out[(((size_t)b * L_ + lt * LT + r1) * H_ + h) * D_ + d] = acc1 * n1;
}

extern "C" void kernel_launch(void* const* d_in, const int* in_sizes, int n_in,
                              void* d_out, int out_size)
{
    const float* q    = (const float*)d_in[0];   // (B,L,H,E)
    const float* k    = (const float*)d_in[1];   // (B,S,H,E)
    const float* vals = (const float*)d_in[2];   // (B,S,H,D)
    const float* v    = (const float*)d_in[3];   // (E,)
    const float* mask = (const float*)d_in[4];   // (L,S)
    const float* klen = (const float*)d_in[5];   // (B,S)
    float* out = (float*)d_out;                  // (B,L,H,D)

    addattn_kernel<<<B_ * H_ * (L_ / LT), 512>>>(q, k, v, vals, mask, klen, out);
}

// round 17
// speedup vs baseline: 1.4842x; 1.0280x over previous
#include <cuda_runtime.h>

#define B_ 2
#define L_ 512
#define S_ 512
#define H_ 8
#define E_ 32
#define D_ 64
#define LT 16        // L rows per block
#define ST 128       // S tile for V in AV phase
#define VPAD 132     // V_shT row stride (mult of 4, mod 32 == 4)

__device__ __forceinline__ float fast_ex2(float x) {
    float r; asm("ex2.approx.f32 %0, %1;" : "=f"(r) : "f"(x)); return r;
}
__device__ __forceinline__ float fast_rcp(float x) {
    float r; asm("rcp.approx.f32 %0, %1;" : "=f"(r) : "f"(x)); return r;
}

// Fused additive attention. tanh via separable exp AND pairwise-combined
// reciprocals:
//   v0/t0 + v1/t1 = ((v0+v1) + (v0*Ek1)*Eq1 + (v1*Ek0)*Eq0) / (t0*t1),
//   t_i = 1 + Eq_i*Ek_i,  Eq=exp2(C q), Ek=exp2(C k), C = 2/ln2.
// -> 0.5 MUFU + 3 FMA-pipe ops per score element.
// Block = (b, h, 16 L rows); 512 threads, thread = s in score phase.
__global__ __launch_bounds__(512, 2) void addattn_kernel(
    const float* __restrict__ q, const float* __restrict__ k,
    const float* __restrict__ v, const float* __restrict__ vals,
    const float* __restrict__ mask, const float* __restrict__ klen,
    float* __restrict__ out)
{
    __shared__ float eq_sh[LT * E_];       // exp2(C*q), [l][e]
    __shared__ float v_sh[E_];
    __shared__ float s_sc[LT][S_];         // scores -> exp(p), 32 KB
    __shared__ float row_red[LT];
    __shared__ float V_shT[D_][VPAD];      // transposed V tile, 33 KB

    const int tid = threadIdx.x;           // = s in score phase
    const int bid = blockIdx.x;
    const int lt = bid & 31;               // 32 L-tiles
    const int h  = (bid >> 5) & 7;
    const int b  = bid >> 8;
    const float C = 2.885390082f;          // 2/ln2

    // ---- stage q (as exp2) and v into shared ----------------------------
    {
        const int l = tid >> 5, e = tid & 31;
        eq_sh[tid] = fast_ex2(
            C * q[(((size_t)b * L_ + (lt * LT + l)) * H_ + h) * E_ + e]);
    }
    if (tid < E_) v_sh[tid] = v[tid];
    __syncthreads();

    float vsum = 0.f;
#pragma unroll
    for (int e = 0; e < E_; e++) vsum += v_sh[e];
    const float base_s = vsum + klen[b * S_ + tid];

    const float4* kp = reinterpret_cast<const float4*>(
        k + (((size_t)b * S_ + tid) * H_ + h) * E_);

    // ---- scores: acc[l] = sum_e v_e / t_e  via pair-combined rcp ---------
    float acc[LT];
#pragma unroll
    for (int l = 0; l < LT; l++) acc[l] = 0.f;

#pragma unroll
    for (int e4 = 0; e4 < E_ / 4; e4++) {
        const float4 kt = kp[e4];
        const float ek0 = fast_ex2(C * kt.x);
        const float ek1 = fast_ex2(C * kt.y);
        const float ek2 = fast_ex2(C * kt.z);
        const float ek3 = fast_ex2(C * kt.w);
        const float4 v4 = *reinterpret_cast<const float4*>(&v_sh[e4 * 4]);
        // pair (0,1)
        const float v01 = v4.x + v4.y;
        const float a0 = v4.y * ek0;       // multiplies Eq0
        const float a1 = v4.x * ek1;       // multiplies Eq1
        // pair (2,3)
        const float v23 = v4.z + v4.w;
        const float a2 = v4.w * ek2;
        const float a3 = v4.z * ek3;
#pragma unroll
        for (int l = 0; l < LT; l++) {
            const float4 eq4 = *reinterpret_cast<const float4*>(
                &eq_sh[l * E_ + e4 * 4]);
            // pair (0,1)
            float t0 = fmaf(eq4.x, ek0, 1.f);
            float t1 = fmaf(eq4.y, ek1, 1.f);
            float n01 = fmaf(eq4.x, a0, fmaf(eq4.y, a1, v01));
            float d01 = t0 * t1;
            // pair (2,3)
            float t2 = fmaf(eq4.z, ek2, 1.f);
            float t3 = fmaf(eq4.w, ek3, 1.f);
            float n23 = fmaf(eq4.z, a2, fmaf(eq4.w, a3, v23));
            float d23 = t2 * t3;
            acc[l] = fmaf(n01, fast_rcp(d01), acc[l]);
            acc[l] = fmaf(n23, fast_rcp(d23), acc[l]);
        }
    }

    // sc = (vsum + klen) - 2*acc + mask
#pragma unroll
    for (int l = 0; l < LT; l++) {
        s_sc[l][tid] = fmaf(-2.f, acc[l], base_s)
                     + mask[(size_t)(lt * LT + l) * S_ + tid];
    }
    __syncthreads();

    // ---- fused max + exp + sum: warp w owns row w ------------------------
    {
        const int warp = tid >> 5, lane = tid & 31;
        float x[S_ / 32];
#pragma unroll
        for (int j = 0; j < S_ / 32; j++) x[j] = s_sc[warp][lane + 32 * j];

        float mx = x[0];
#pragma unroll
        for (int j = 1; j < S_ / 32; j++) mx = fmaxf(mx, x[j]);
#pragma unroll
        for (int off = 16; off; off >>= 1)
            mx = fmaxf(mx, __shfl_xor_sync(0xffffffffu, mx, off));

        float s = 0.f;
#pragma unroll
        for (int j = 0; j < S_ / 32; j++) {
            float p = fast_ex2((x[j] - mx) * 1.442695041f);
            s_sc[warp][lane + 32 * j] = p;
            s += p;
        }
#pragma unroll
        for (int off = 16; off; off >>= 1)
            s += __shfl_xor_sync(0xffffffffu, s, off);
        if (lane == 0) row_red[warp] = fast_rcp(s);
    }
    __syncthreads();

    // ---- AV: out[16][64] = P[16][512] @ V[512][64], normalize at end -----
    const int d  = tid & 63;
    const int rg = tid >> 6;               // 0..7, owns rows 2rg, 2rg+1
    const int r0 = rg * 2, r1 = r0 + 1;
    float acc0 = 0.f, acc1 = 0.f;

    for (int st = 0; st < S_ / ST; st++) {
        // V tile transposed: V_shT[d][s]; LDS.128 reads conflict-free.
#pragma unroll
        for (int i = 0; i < (ST * D_) / 512; i++) {   // 16 elems/thread
            int idx = tid + i * 512;
            int srow = idx >> 6, dcol = idx & 63;
            V_shT[dcol][srow] =
                vals[(((size_t)b * S_ + st * ST + srow) * H_ + h) * D_ + dcol];
        }
        __syncthreads();

#pragma unroll 8
        for (int s4 = 0; s4 < ST / 4; s4++) {
            float4 a0 = *reinterpret_cast<const float4*>(&s_sc[r0][st * ST + s4 * 4]);
            float4 a1 = *reinterpret_cast<const float4*>(&s_sc[r1][st * ST + s4 * 4]);
            float4 vv = *reinterpret_cast<const float4*>(&V_shT[d][s4 * 4]);
            acc0 = fmaf(a0.x, vv.x, fmaf(a0.y, vv.y,
                   fmaf(a0.z, vv.z, fmaf(a0.w, vv.w, acc0))));
            acc1 = fmaf(a1.x, vv.x, fmaf(a1.y, vv.y,
                   fmaf(a1.z, vv.z, fmaf(a1.w, vv.w, acc1))));
        }
        __syncthreads();
    }

    const float n0 = row_red[r0], n1 = row_red[r1];
    out[(((size_t)b * L_ + lt * LT + r0) * H_ + h) * D_ + d] = acc0 * n0;
    out[(((size_t)b * L_ + lt * LT + r1) * H_ + h) * D_ + d] = acc1 * n1;
}

extern "C" void kernel_launch(void* const* d_in, const int* in_sizes, int n_in,
                              void* d_out, int out_size)
{
    const float* q    = (const float*)d_in[0];   // (B,L,H,E)
    const float* k    = (const float*)d_in[1];   // (B,S,H,E)
    const float* vals = (const float*)d_in[2];   // (B,S,H,D)
    const float* v    = (const float*)d_in[3];   // (E,)
    const float* mask = (const float*)d_in[4];   // (L,S)
    const float* klen = (const float*)d_in[5];   // (B,S)
    float* out = (float*)d_out;                  // (B,L,H,D)

    addattn_kernel<<<B_ * H_ * (L_ / LT), 512>>>(q, k, v, vals, mask, klen, out);
}